// round 2
// baseline (speedup 1.0000x reference)
#include <cuda_runtime.h>
#include <cuda_bf16.h>

// word_vecs [B=2048, S=200, D=300] fp32 -> masked mean over S -> [B, D].
// All-zero (masked) words contribute 0 to the sum, so only the COUNT needs the
// mask. Count path: per-thread 16-bit nonzero bitmask per 16-word chunk
// (compile-time shifts -> registers), one warp OR-reduce + shared atomicOr per
// chunk, popc at the end. Note padding can contain -0.0f (x * 0.0f in the
// reference), so the nonzero test clears the sign bit before comparing.

#define B_DIM 2048
#define S_DIM 200
#define VDIM  75      // 300 floats = 75 float4 (1200 B row, 16B aligned)
#define NTHREADS 96
#define BLK   16
#define NFULL 12      // 12 * 16 = 192 words
#define TAIL  8       // + 8 = 200
#define NCHUNK 13

__device__ __forceinline__ unsigned f4_nzbits(float4 v) {
    // OR of all 4 bit patterns with sign bits cleared: nonzero iff any
    // component is a nonzero float (treats -0.0f as zero, like `!= 0`).
    unsigned a = __float_as_uint(v.x) | __float_as_uint(v.y);
    unsigned b = __float_as_uint(v.z) | __float_as_uint(v.w);
    return (a | b) & 0x7fffffffu;
}

__global__ __launch_bounds__(NTHREADS)
void sentence_rep_kernel(const float4* __restrict__ in, float4* __restrict__ out) {
    __shared__ unsigned orbits[NCHUNK];
    __shared__ float inv_count;

    const int b = blockIdx.x;
    const int t = threadIdx.x;
    const bool active = (t < VDIM);
    const int lane = t & 31;

    if (t < NCHUNK) orbits[t] = 0u;
    __syncthreads();

    const float4* __restrict__ p = in + (size_t)b * (S_DIM * VDIM) + t;

    float4 acc = make_float4(0.f, 0.f, 0.f, 0.f);

    #pragma unroll 1
    for (int blk = 0; blk < NFULL; ++blk) {
        unsigned m = 0u;
        #pragma unroll
        for (int i = 0; i < BLK; ++i) {
            float4 v = make_float4(0.f, 0.f, 0.f, 0.f);
            if (active) v = __ldcs(p + i * VDIM);
            acc.x += v.x; acc.y += v.y; acc.z += v.z; acc.w += v.w;
            if (f4_nzbits(v)) m |= (1u << i);
        }
        unsigned w = __reduce_or_sync(0xffffffffu, m);
        if (lane == 0 && w) atomicOr(&orbits[blk], w);
        p += BLK * VDIM;
    }
    {   // tail: words 192..199
        unsigned m = 0u;
        #pragma unroll
        for (int i = 0; i < TAIL; ++i) {
            float4 v = make_float4(0.f, 0.f, 0.f, 0.f);
            if (active) v = __ldcs(p + i * VDIM);
            acc.x += v.x; acc.y += v.y; acc.z += v.z; acc.w += v.w;
            if (f4_nzbits(v)) m |= (1u << i);
        }
        unsigned w = __reduce_or_sync(0xffffffffu, m);
        if (lane == 0 && w) atomicOr(&orbits[NFULL], w);
    }
    __syncthreads();

    if (t < 32) {
        unsigned v = (t < NCHUNK) ? orbits[t] : 0u;
        int c = __popc(v);
        c = __reduce_add_sync(0xffffffffu, c);
        if (t == 0) inv_count = 1.0f / (float)c;   // count >= 1 guaranteed
    }
    __syncthreads();

    if (active) {
        const float ic = inv_count;
        out[(size_t)b * VDIM + t] =
            make_float4(acc.x * ic, acc.y * ic, acc.z * ic, acc.w * ic);
    }
}

extern "C" void kernel_launch(void* const* d_in, const int* in_sizes, int n_in,
                              void* d_out, int out_size) {
    (void)in_sizes; (void)n_in; (void)out_size;
    const float4* in = (const float4*)d_in[0];
    float4* out = (float4*)d_out;
    sentence_rep_kernel<<<B_DIM, NTHREADS>>>(in, out);
}